// round 2
// baseline (speedup 1.0000x reference)
#include <cuda_runtime.h>
#include <cuda_bf16.h>
#include <mma.h>
#include <math.h>
#include <stdint.h>

using namespace nvcuda;

// Problem sizes: S=40, B=32, T=40, E=256, H=512, V=50000
// rows for decoder outputs: (T-1)*B = 39*32 = 1248, padded to 1280
#define NTILES 391   // 50048/128 vocab tiles

// ---------------- scratch (static device arrays; no allocation) ----------------
__device__ float g_srce [1280*256];
__device__ float g_srcer[1280*256];
__device__ float g_tgte [1280*256];
__device__ float g_xf   [1280*2048];
__device__ float g_xb   [1280*2048];
__device__ float g_xe   [1280*2048];
__device__ float g_henc [2*2*32*512];   // [par][dir][b][512]
__device__ float g_cenc [2*32*512];     // [dir][b][512]
__device__ float g_ench [32*40*1024];   // [b][s][2H]
__device__ float g_encp [32*40*512];    // [b][s][H]
__device__ float g_hcc  [32*1024];
__device__ float g_ccc  [32*1024];
__device__ float g_hcat [2*32*1024];    // [par][b][h|o_prev]
__device__ float g_cdec [32*512];
__device__ float g_kcat [32*1536];      // [b][h|ctx]
__device__ float g_Wdr  [2048*1024];    // combined [Whh | Wih_o]
__device__ __nv_bfloat16 g_outsb[1280*512];
__device__ __nv_bfloat16 g_wvb  [50048ull*512];
__device__ float g_pmax [1248*NTILES];
__device__ float g_psum [1248*NTILES];
__device__ float g_pick [1248];
__device__ float g_plogp[1248];

__device__ __forceinline__ float sigf(float x){ return 1.f/(1.f+expf(-x)); }

// ---------------- prep ----------------
__global__ void k_prep(const float* dWih, const float* dWhh){
    size_t stride = (size_t)gridDim.x*blockDim.x;
    size_t id0 = (size_t)blockIdx.x*blockDim.x + threadIdx.x;
    for (size_t i=id0; i<2048ull*1024; i+=stride){
        int n = (int)(i>>10), k = (int)(i&1023);
        g_Wdr[i] = (k<512) ? dWhh[(size_t)n*512+k] : dWih[(size_t)n*768 + 256 + (k-512)];
    }
    for (size_t i=id0; i<2ull*2*32*512; i+=stride) g_henc[i]=0.f;
    for (size_t i=id0; i<2ull*32*512;   i+=stride) g_cenc[i]=0.f;
    for (size_t i=id0; i<32ull*512;     i+=stride) g_cdec[i]=0.f;
    for (size_t i=id0; i<32ull*512;     i+=stride)
        g_hcat[(i>>9)*1024 + 512 + (i&511)] = 0.f;          // o0 = 0 in hcat[0]
    for (size_t i=id0; i<32ull*512;     i+=stride)
        g_outsb[1248ull*512 + i] = __float2bfloat16(0.f);   // pad rows
}

__global__ void k_wvb(const float* Wv){
    size_t stride = (size_t)gridDim.x*blockDim.x;
    for (size_t i=(size_t)blockIdx.x*blockDim.x+threadIdx.x; i<50048ull*512; i+=stride){
        size_t v = i >> 9;
        g_wvb[i] = __float2bfloat16(v < 50000 ? Wv[i] : 0.f);
    }
}

__global__ void k_gather(const int* src, const int* tgt, const float* se, const float* te){
    size_t stride = (size_t)gridDim.x*blockDim.x;
    for (size_t i=(size_t)blockIdx.x*blockDim.x+threadIdx.x; i<(size_t)(1280+1280+1248)*256; i+=stride){
        int k = (int)(i & 255); size_t m = i >> 8;
        if (m < 1280) g_srce[m*256+k] = se[(size_t)src[m]*256+k];
        else if (m < 2560){
            size_t mm = m-1280; int tt=(int)(mm>>5), bb=(int)(mm&31);
            g_srcer[mm*256+k] = se[(size_t)src[(39-tt)*32+bb]*256+k];
        } else {
            size_t mm = m-2560;
            g_tgte[mm*256+k] = te[(size_t)tgt[mm]*256+k];
        }
    }
}

// ---------------- generic fp32 GEMM: C[M][N] = A[M][K] @ W[N][K]^T (+bias) ----------------
__global__ void __launch_bounds__(256) k_gemm(const float* A, int lda, const float* W, int ldw,
        const float* bias, float* C, int ldc, int M, int N, int K){
    int m0 = blockIdx.x*64, n0 = blockIdx.y*64;
    int tid = threadIdx.x, tx = tid&15, ty = tid>>4;
    __shared__ float As[64][33], Bs[64][33];
    float acc[4][4] = {};
    for (int k0=0; k0<K; k0+=32){
        #pragma unroll
        for (int p=0;p<8;p++){
            int idx = tid + p*256; int r = idx>>5, kk = idx&31;
            As[r][kk] = (m0+r < M) ? A[(size_t)(m0+r)*lda + k0 + kk] : 0.f;
            Bs[r][kk] = (n0+r < N) ? W[(size_t)(n0+r)*ldw + k0 + kk] : 0.f;
        }
        __syncthreads();
        #pragma unroll
        for (int kk=0;kk<32;kk++){
            float av[4], bv[4];
            #pragma unroll
            for (int i=0;i<4;i++) av[i] = As[ty*4+i][kk];
            #pragma unroll
            for (int j=0;j<4;j++) bv[j] = Bs[tx*4+j][kk];
            #pragma unroll
            for (int i=0;i<4;i++)
                #pragma unroll
                for (int j=0;j<4;j++) acc[i][j] += av[i]*bv[j];
        }
        __syncthreads();
    }
    #pragma unroll
    for (int i=0;i<4;i++){
        int m = m0 + ty*4 + i; if (m >= M) continue;
        #pragma unroll
        for (int j=0;j<4;j++){
            int n = n0 + tx*4 + j; if (n >= N) continue;
            C[(size_t)m*ldc + n] = acc[i][j] + (bias ? bias[n] : 0.f);
        }
    }
}

// ---------------- encoder step: gates = x_t + h@Whh^T, fused LSTM cell ----------------
__global__ void __launch_bounds__(256) k_enc_step(int t, const float* Whh_f, const float* Whh_b){
    int dir = blockIdx.y, j0 = blockIdx.x*8;
    int tid = threadIdx.x, b = tid&31, u = tid>>5;   // u in 0..7
    const float* W = dir ? Whh_b : Whh_f;
    int par = t & 1;
    const float* hin = g_henc + (size_t)(par*2 + dir)*32*512;
    __shared__ float Hs[64][33];
    __shared__ float Ws[32][72];
    float a0=0,a1=0,a2=0,a3=0;
    for (int k0=0;k0<512;k0+=64){
        #pragma unroll
        for (int p=0;p<8;p++){
            int idx = tid + p*256; int bb = idx>>6, kk = idx&63;
            Hs[kk][bb] = hin[bb*512 + k0 + kk];
        }
        {
            int r = tid>>3, kq = (tid&7)*8;
            int grow = (r>>3)*512 + j0 + (r&7);
            *(float4*)&Ws[r][kq]   = *(const float4*)&W[(size_t)grow*512 + k0 + kq];
            *(float4*)&Ws[r][kq+4] = *(const float4*)&W[(size_t)grow*512 + k0 + kq + 4];
        }
        __syncthreads();
        #pragma unroll
        for (int kk=0;kk<64;kk++){
            float hv = Hs[kk][b];
            a0 += hv*Ws[u][kk];
            a1 += hv*Ws[8+u][kk];
            a2 += hv*Ws[16+u][kk];
            a3 += hv*Ws[24+u][kk];
        }
        __syncthreads();
    }
    int j = j0 + u;
    const float* xr = (dir ? g_xb : g_xf) + ((size_t)t*32 + b)*2048;
    float gi = sigf (a0 + xr[j]);
    float gf = sigf (a1 + xr[512+j]);
    float gg = tanhf(a2 + xr[1024+j]);
    float go = sigf (a3 + xr[1536+j]);
    float* cst = g_cenc + (size_t)(dir*32 + b)*512 + j;
    float cn = gf*(*cst) + gi*gg;
    *cst = cn;
    float hn = go * tanhf(cn);
    g_henc[((size_t)((1-par)*2 + dir)*32 + b)*512 + j] = hn;
    int s = dir ? (39 - t) : t;
    g_ench[((size_t)b*40 + s)*1024 + dir*512 + j] = hn;
}

__global__ void k_mkcat(){
    int i = blockIdx.x*blockDim.x + threadIdx.x;
    if (i < 32*1024){
        int b = i>>10, k = i&1023; int dir = k>>9, kk = k&511;
        g_hcc[i] = g_henc[((size_t)(0*2+dir)*32 + b)*512 + kk];   // par==0 after t=39
        g_ccc[i] = g_cenc[((size_t)dir*32 + b)*512 + kk];
    }
}

// ---------------- decoder step 1: gates = xe_t + [h|o_prev]@Wdr^T, fused cell ----------------
__global__ void __launch_bounds__(128) k_dec_step1(int t){
    int j0 = blockIdx.x*4;
    int tid = threadIdx.x, b = tid&31, u = tid>>5;   // u in 0..3
    int par = t & 1;
    const float* hin = g_hcat + (size_t)par*32*1024;
    __shared__ float Hs[64][33];
    __shared__ float Ws[16][72];
    float a0=0,a1=0,a2=0,a3=0;
    for (int k0=0;k0<1024;k0+=64){
        #pragma unroll
        for (int p=0;p<16;p++){
            int idx = tid + p*128; int bb = idx>>6, kk = idx&63;
            Hs[kk][bb] = hin[bb*1024 + k0 + kk];
        }
        {
            int r = tid>>3, kq = (tid&7)*8;
            int grow = (r>>2)*512 + j0 + (r&3);
            *(float4*)&Ws[r][kq]   = *(const float4*)&g_Wdr[(size_t)grow*1024 + k0 + kq];
            *(float4*)&Ws[r][kq+4] = *(const float4*)&g_Wdr[(size_t)grow*1024 + k0 + kq + 4];
        }
        __syncthreads();
        #pragma unroll
        for (int kk=0;kk<64;kk++){
            float hv = Hs[kk][b];
            a0 += hv*Ws[u][kk];
            a1 += hv*Ws[4+u][kk];
            a2 += hv*Ws[8+u][kk];
            a3 += hv*Ws[12+u][kk];
        }
        __syncthreads();
    }
    int j = j0 + u;
    const float* xr = g_xe + ((size_t)t*32 + b)*2048;
    float gi = sigf (a0 + xr[j]);
    float gf = sigf (a1 + xr[512+j]);
    float gg = tanhf(a2 + xr[1024+j]);
    float go = sigf (a3 + xr[1536+j]);
    float* cst = g_cdec + (size_t)b*512 + j;
    float cn = gf*(*cst) + gi*gg;
    *cst = cn;
    float hn = go * tanhf(cn);
    g_kcat[(size_t)b*1536 + j] = hn;
    g_hcat[((size_t)(1-par)*32 + b)*1024 + j] = hn;
}

// ---------------- attention: scores -> softmax -> ctx ----------------
__global__ void __launch_bounds__(256) k_att(const float* masks){
    int b = blockIdx.x, tid = threadIdx.x, lane = tid&31, w = tid>>5;
    __shared__ float hv[512], sc[40];
    for (int i=tid;i<512;i+=256) hv[i] = g_kcat[(size_t)b*1536 + i];
    __syncthreads();
    #pragma unroll
    for (int q=0;q<5;q++){
        int s = w*5 + q;
        const float* ep = g_encp + ((size_t)b*40 + s)*512;
        float p = 0.f;
        for (int k=lane;k<512;k+=32) p += ep[k]*hv[k];
        #pragma unroll
        for (int o=16;o;o>>=1) p += __shfl_down_sync(0xffffffffu, p, o);
        if (!lane) sc[s] = (masks[b*40 + s] > 0.f) ? -INFINITY : p;
    }
    __syncthreads();
    if (tid == 0){
        float m = -INFINITY;
        for (int s=0;s<40;s++) m = fmaxf(m, sc[s]);
        float sum = 0.f;
        for (int s=0;s<40;s++){ float e = expf(sc[s]-m); sc[s]=e; sum+=e; }
        float inv = 1.f/sum;
        for (int s=0;s<40;s++) sc[s] *= inv;
    }
    __syncthreads();
    for (int jj=tid;jj<1024;jj+=256){
        float acc = 0.f;
        #pragma unroll 8
        for (int s=0;s<40;s++) acc += sc[s]*g_ench[((size_t)b*40 + s)*1024 + jj];
        g_kcat[(size_t)b*1536 + 512 + jj] = acc;
    }
}

// ---------------- o_t = tanh([h|ctx] @ W_comb^T); write hcat + outs(bf16) ----------------
__global__ void __launch_bounds__(256) k_comb(int t, const float* Wc){
    int n0 = blockIdx.x*32;
    int tid = threadIdx.x, b = tid&31, ng = tid>>5;  // ng in 0..7
    __shared__ float Hs[64][33];
    __shared__ float Ws[32][72];
    float a[4] = {0,0,0,0};
    for (int k0=0;k0<1536;k0+=64){
        #pragma unroll
        for (int p=0;p<8;p++){
            int idx = tid + p*256; int bb = idx>>6, kk = idx&63;
            Hs[kk][bb] = g_kcat[(size_t)bb*1536 + k0 + kk];
        }
        {
            int r = tid>>3, kq = (tid&7)*8;
            *(float4*)&Ws[r][kq]   = *(const float4*)&Wc[(size_t)(n0+r)*1536 + k0 + kq];
            *(float4*)&Ws[r][kq+4] = *(const float4*)&Wc[(size_t)(n0+r)*1536 + k0 + kq + 4];
        }
        __syncthreads();
        #pragma unroll
        for (int kk=0;kk<64;kk++){
            float hvv = Hs[kk][b];
            #pragma unroll
            for (int q=0;q<4;q++) a[q] += hvv*Ws[ng*4+q][kk];
        }
        __syncthreads();
    }
    int par = t & 1;
    #pragma unroll
    for (int q=0;q<4;q++){
        int n = n0 + ng*4 + q;
        float v = tanhf(a[q]);
        g_hcat[((size_t)(1-par)*32 + b)*1024 + 512 + n] = v;
        g_outsb[((size_t)t*32 + b)*512 + n] = __float2bfloat16(v);
    }
}

// ---------------- fused vocab GEMM (bf16 wmma) + partial logsumexp + pick ----------------
__global__ void __launch_bounds__(256) k_vocab(const int* tgt){
    int vt = blockIdx.x, rt = blockIdx.y;
    int tid = threadIdx.x, w = tid>>5;
    int wr = w>>2, wv = w&3;
    __shared__ float ls[64][132];
    wmma::fragment<wmma::matrix_a,16,16,16,__nv_bfloat16,wmma::row_major> af[2];
    wmma::fragment<wmma::matrix_b,16,16,16,__nv_bfloat16,wmma::col_major> bf[2];
    wmma::fragment<wmma::accumulator,16,16,16,float> cf[2][2];
    #pragma unroll
    for (int i=0;i<2;i++)
        #pragma unroll
        for (int j=0;j<2;j++) wmma::fill_fragment(cf[i][j], 0.f);
    const __nv_bfloat16* Ab = g_outsb + ((size_t)rt*64 + wr*32)*512;
    const __nv_bfloat16* Bb = g_wvb  + ((size_t)vt*128 + wv*32)*512;
    for (int k=0;k<512;k+=16){
        wmma::load_matrix_sync(af[0], Ab + k,           512);
        wmma::load_matrix_sync(af[1], Ab + 16*512 + k,  512);
        wmma::load_matrix_sync(bf[0], Bb + k,           512);
        wmma::load_matrix_sync(bf[1], Bb + 16*512 + k,  512);
        #pragma unroll
        for (int i=0;i<2;i++)
            #pragma unroll
            for (int j=0;j<2;j++) wmma::mma_sync(cf[i][j], af[i], bf[j], cf[i][j]);
    }
    #pragma unroll
    for (int i=0;i<2;i++)
        #pragma unroll
        for (int j=0;j<2;j++)
            wmma::store_matrix_sync(&ls[wr*32+i*16][wv*32+j*16], cf[i][j], 132, wmma::mem_row_major);
    __syncthreads();
    if (tid < 64){
        int m = rt*64 + tid;
        if (m < 1248){
            int v0 = vt*128;
            int valid = min(128, 50000 - v0);
            float mx = -INFINITY;
            for (int c=0;c<valid;c++) mx = fmaxf(mx, ls[tid][c]);
            float s = 0.f;
            for (int c=0;c<valid;c++) s += expf(ls[tid][c]-mx);
            g_pmax[(size_t)m*NTILES + vt] = mx;
            g_psum[(size_t)m*NTILES + vt] = s;
            int tv = tgt[m + 32];
            if (tv >= v0 && tv < v0+valid) g_pick[m] = ls[tid][tv - v0];
        }
    }
}

__global__ void k_lse(const int* tgt){
    int m = blockIdx.x*blockDim.x + threadIdx.x;
    if (m >= 1248) return;
    float mx = -INFINITY, s = 0.f;
    for (int j=0;j<NTILES;j++){
        float pm = g_pmax[(size_t)m*NTILES + j], ps = g_psum[(size_t)m*NTILES + j];
        if (pm > mx){ s = s*expf(mx-pm) + ps; mx = pm; }
        else s += ps*expf(pm-mx);
    }
    float lse = mx + logf(s);
    int tv = tgt[m + 32];
    g_plogp[m] = (tv != 0) ? (g_pick[m] - lse) : 0.f;
}

__global__ void k_out(float* out){
    int b = threadIdx.x;
    if (b < 32){
        float s = 0.f;
        for (int t=0;t<39;t++) s += g_plogp[t*32 + b];
        out[b] = s;
    }
}

// ---------------- launch ----------------
extern "C" void kernel_launch(void* const* d_in, const int* in_sizes, int n_in,
                              void* d_out, int out_size){
    const int*   src   = (const int*)d_in[0];
    const int*   tgt   = (const int*)d_in[1];
    const float* masks = (const float*)d_in[2];
    const float* se    = (const float*)d_in[3];
    const float* te    = (const float*)d_in[4];
    const float* eWif  = (const float*)d_in[5];
    const float* eWhf  = (const float*)d_in[6];
    const float* ebf   = (const float*)d_in[7];
    const float* eWib  = (const float*)d_in[8];
    const float* eWhb  = (const float*)d_in[9];
    const float* ebb   = (const float*)d_in[10];
    const float* dWih  = (const float*)d_in[11];
    const float* dWhh  = (const float*)d_in[12];
    const float* db    = (const float*)d_in[13];
    const float* Wh    = (const float*)d_in[14];
    const float* Wc    = (const float*)d_in[15];
    const float* Watt  = (const float*)d_in[16];
    const float* Wcomb = (const float*)d_in[17];
    const float* Wv    = (const float*)d_in[18];

    float *p_srce,*p_srcer,*p_tgte,*p_xf,*p_xb,*p_xe,*p_ench,*p_encp,*p_hcc,*p_ccc,*p_hcat,*p_cdec;
    cudaGetSymbolAddress((void**)&p_srce,  g_srce);
    cudaGetSymbolAddress((void**)&p_srcer, g_srcer);
    cudaGetSymbolAddress((void**)&p_tgte,  g_tgte);
    cudaGetSymbolAddress((void**)&p_xf,    g_xf);
    cudaGetSymbolAddress((void**)&p_xb,    g_xb);
    cudaGetSymbolAddress((void**)&p_xe,    g_xe);
    cudaGetSymbolAddress((void**)&p_ench,  g_ench);
    cudaGetSymbolAddress((void**)&p_encp,  g_encp);
    cudaGetSymbolAddress((void**)&p_hcc,   g_hcc);
    cudaGetSymbolAddress((void**)&p_ccc,   g_ccc);
    cudaGetSymbolAddress((void**)&p_hcat,  g_hcat);
    cudaGetSymbolAddress((void**)&p_cdec,  g_cdec);

    k_prep<<<1024,256>>>(dWih, dWhh);
    k_wvb<<<2048,256>>>(Wv);
    k_gather<<<2048,256>>>(src, tgt, se, te);

    // input-side GEMMs (hoisted out of the recurrences)
    k_gemm<<<dim3(20,32),256>>>(p_srce, 256, eWif, 256, ebf, p_xf, 2048, 1280, 2048, 256);
    k_gemm<<<dim3(20,32),256>>>(p_srcer,256, eWib, 256, ebb, p_xb, 2048, 1280, 2048, 256);
    k_gemm<<<dim3(20,32),256>>>(p_tgte, 256, dWih, 768, db,  p_xe, 2048, 1248, 2048, 256);

    for (int t=0;t<40;t++) k_enc_step<<<dim3(64,2),256>>>(t, eWhf, eWhb);

    k_mkcat<<<128,256>>>();
    k_gemm<<<dim3(1,8),256>>>(p_hcc, 1024, Wh, 1024, nullptr, p_hcat, 1024, 32, 512, 1024);
    k_gemm<<<dim3(1,8),256>>>(p_ccc, 1024, Wc, 1024, nullptr, p_cdec, 512,  32, 512, 1024);
    k_gemm<<<dim3(20,8),256>>>(p_ench, 1024, Watt, 1024, nullptr, p_encp, 512, 1280, 512, 1024);

    for (int t=0;t<39;t++){
        k_dec_step1<<<128,128>>>(t);
        k_att<<<32,256>>>(masks);
        k_comb<<<16,256>>>(t, Wcomb);
    }

    k_vocab<<<dim3(NTILES,20),256>>>(tgt);
    k_lse<<<10,128>>>(tgt);
    k_out<<<1,32>>>((float*)d_out);
}